// round 6
// baseline (speedup 1.0000x reference)
#include <cuda_runtime.h>
#include <math.h>

#define NB 8
#define NM 4
#define NN 25
#define NT 255
#define DD 3201
#define INNER 3200
#define PROW 6375          // NT*NN, per (h,n) table row
#define WSPAN 4700         // 60*25 + 3200 : window span for 16 rows spaced 4
#define SHPSZ 4708         // WSPAN + 3 (sigma) + pad

// scratch (static device globals — no allocation)
static __device__ __align__(16) float g_P2[NM * NN * PROW];
static __device__ float g_dvec[NM * DD];

__device__ __forceinline__ float warp_iscan(float v) {
    int lane = threadIdx.x & 31;
    #pragma unroll
    for (int o = 1; o < 32; o <<= 1) {
        float u = __shfl_up_sync(0xffffffffu, v, o);
        if (lane >= o) v += u;
    }
    return v;
}

// ---------------- K1: fused g + P2 + prefix-scan row sums + d --------------
__global__ __launch_bounds__(256) void pm_k_main(
    const float* __restrict__ mat, const float* __restrict__ te,
    const float* __restrict__ W, const float* __restrict__ bias,
    const float* __restrict__ minit)
{
    __shared__ __align__(16) float sh[PROW + 1];
    __shared__ __align__(16) float gsh[NT * NB];
    __shared__ float matsh[NB * NN];
    __shared__ float P[256];
    __shared__ float Q[256];
    __shared__ float wA[8], wB[8], wAo[8], wBo[8];
    __shared__ float s_c127, s_v127;

    int bid = blockIdx.x;
    int tid = threadIdx.x;
    int lane = tid & 31, wid = tid >> 5;

    if (bid >= 100) {                 // row-0 degree: sum of minit row 0
        int h = bid - 100;
        const float* m0 = minit + (size_t)h * DD * DD;
        float s = 0.0f;
        for (int c = tid; c < DD; c += 256) s += m0[c];
        #pragma unroll
        for (int o = 16; o; o >>= 1) s += __shfl_down_sync(0xffffffffu, s, o);
        if (lane == 0) wA[wid] = s;
        __syncthreads();
        if (wid == 0) {
            s = (lane < 8) ? wA[lane] : 0.0f;
            #pragma unroll
            for (int o = 4; o; o >>= 1) s += __shfl_down_sync(0xffffffffu, s, o);
            if (lane == 0) g_dvec[h * DD] = rsqrtf(fmaxf(s, 1.0f));
        }
        return;
    }

    int h = bid / NN, n = bid % NN;

    for (int idx = tid; idx < NT * NB; idx += 256) {
        int b = idx & 7, t = idx >> 3;
        gsh[idx] = W[h * NB + b] / (1.0f + expf(-te[b * NT + t]));
    }
    for (int idx = tid; idx < NB * NN; idx += 256)
        matsh[idx] = mat[(idx / NN) * NN * NN + n * NN + (idx % NN)];
    __syncthreads();

    float a = 0.0f, b = 0.0f;
    if (tid < NT) {
        float bh = bias[h];
        const float4* gp = reinterpret_cast<const float4*>(gsh + tid * NB);
        float4 g0 = gp[0], g1 = gp[1];
        int base = tid * NN;
        #pragma unroll
        for (int m = 0; m < NN; m++) {
            float acc = bh;
            acc += g0.x * matsh[0 * NN + m] + g0.y * matsh[1 * NN + m] +
                   g0.z * matsh[2 * NN + m] + g0.w * matsh[3 * NN + m];
            acc += g1.x * matsh[4 * NN + m] + g1.y * matsh[5 * NN + m] +
                   g1.z * matsh[6 * NN + m] + g1.w * matsh[7 * NN + m];
            float v = fmaxf(acc, 0.0f);
            sh[base + m] = v;
            a += v;
            if (m == NN - 1) b = v;
        }
    }
    if (tid == 127) { s_c127 = a; s_v127 = b; }

    float ia = warp_iscan(a);
    float ib = warp_iscan(b);
    if (lane == 31) { wA[wid] = ia; wB[wid] = ib; }
    __syncthreads();
    if (tid == 0) {
        float sa = 0.0f, sb = 0.0f;
        #pragma unroll
        for (int w = 0; w < 8; w++) { wAo[w] = sa; wBo[w] = sb; sa += wA[w]; sb += wB[w]; }
    }
    __syncthreads();
    P[tid] = ia - a + wAo[wid];
    Q[tid] = ib - b + wBo[wid];

    float* dst = g_P2 + (size_t)(h * NN + n) * PROW;
    for (int e = tid; e < PROW; e += 256) dst[e] = sh[e];
    __syncthreads();

    if (tid < 128) {
        int i = tid;
        int r = 1 + i * NN + n;
        float c0 = minit[(size_t)(h * DD + r) * DD];
        float sum;
        if (n == NN - 1)
            sum = (Q[255 - i] - Q[127 - i]) + s_c127 - s_v127;
        else
            sum = P[255 - i] - P[127 - i];
        g_dvec[h * DD + r] = rsqrtf(fmaxf(sum + c0, 1.0f));
    }
}

// ---------------- K2: output, phase-grouped rows, k-outer / 8-row inner ----
// grid: 4 row-0 blocks + 800 blocks (h,n,g=i%4,half); 256 threads; 16 rows/blk
__global__ __launch_bounds__(256) void pm_k_out(const float* __restrict__ minit,
                                                float* __restrict__ out)
{
    __shared__ __align__(16) float shp[SHPSZ];
    __shared__ __align__(16) float dvr[3208];   // rotated dv copy
    int bid = blockIdx.x;
    int tid = threadIdx.x;

    if (bid < 4) {
        int h = bid;
        const float* m0 = minit + (size_t)h * DD * DD;
        const float* dvp = g_dvec + h * DD;
        float d0 = dvp[0];
        float* o = out + (size_t)h * DD * DD;
        for (int c = tid; c < DD; c += 256)
            o[c] = m0[c] * d0 * dvp[c];
        return;
    }
    int b2 = bid - 4;
    int h = b2 / 200;
    int rest = b2 % 200;
    int n = rest / 8;
    int sub = rest % 8;
    int g = sub & 3;
    int half = sub >> 2;
    int i_min = g + 64 * half;

    int r0 = 1 + i_min * NN + n;
    int a0 = (4 - ((h + r0) & 3)) & 3;          // head floats to 16B boundary
    int sigma = (1 - a0) & 3;                   // window stage shift
    int E0 = (67 - i_min) * NN;                 // window start in P2 row
    bool masked = (n == NN - 1);

    const float* dvh = g_dvec + h * DD;
    const float* src = g_P2 + (size_t)(h * NN + n) * PROW + E0;
    for (int e = tid; e < WSPAN; e += 256) shp[e + sigma] = src[e];
    if (!masked)
        for (int x = tid; x < DD - a0; x += 256) dvr[x] = dvh[x + a0];
    __syncthreads();

    float d0 = dvh[0];
    int nv = (DD - a0) >> 2;
    int ct = a0 + (nv << 2);
    int sb_extra = (a0 >= 2) ? 4 : 0;           // (sigma + a0 - 1) is 0 or 4

    if (!masked) {
        #pragma unroll
        for (int hf = 0; hf < 2; hf++) {
            float drv[8];
            const float* sp[8];
            float* ob[8];
            #pragma unroll
            for (int j = 0; j < 8; j++) {
                int jj = hf * 8 + j;
                int r = r0 + 100 * jj;
                drv[j] = dvh[r];
                sp[j] = shp + (60 - 4 * jj) * NN + sb_extra;  // vector base (col a0)
                ob[j] = out + ((size_t)h * DD + r) * DD;
            }
            // head: c in [0, a0)
            if (tid < a0) {
                int c = tid;
                #pragma unroll
                for (int j = 0; j < 8; j++) {
                    float v = (c == 0) ? minit[ob[j] - out] * d0
                                       : sp[j][c - a0] * dvh[c];
                    ob[j][c] = v * drv[j];
                }
            }
            // vector body: dq loaded once per k, reused by 8 rows
            for (int k = tid; k < nv; k += 256) {
                const float4 dq = *reinterpret_cast<const float4*>(dvr + (k << 2));
                #pragma unroll
                for (int j = 0; j < 8; j++) {
                    const float4 pv =
                        *reinterpret_cast<const float4*>(sp[j] + (k << 2));
                    float4 w;
                    w.x = pv.x * dq.x * drv[j];
                    w.y = pv.y * dq.y * drv[j];
                    w.z = pv.z * dq.z * drv[j];
                    w.w = pv.w * dq.w * drv[j];
                    *reinterpret_cast<float4*>(ob[j] + a0 + (k << 2)) = w;
                }
            }
            // c==0 fixup when a0==0: tid 0 wrote k==0, same thread re-stores
            if (a0 == 0 && tid == 0) {
                #pragma unroll
                for (int j = 0; j < 8; j++)
                    ob[j][0] = minit[ob[j] - out] * d0 * drv[j];
            }
            // tail: c in [ct, DD)
            for (int c = ct + tid; c < DD; c += 256) {
                #pragma unroll
                for (int j = 0; j < 8; j++)
                    ob[j][c] = sp[j][c - a0] * dvh[c] * drv[j];
            }
        }
    } else {
        // pass 1: zeros (vectorized), with c==0 value
        for (int jj = 0; jj < 16; jj++) {
            int i = i_min + 4 * jj;
            int r = 1 + i * NN + n;
            float dr = dvh[r];
            float c0v = minit[(size_t)(h * DD + r) * DD];
            float* o = out + (size_t)(h * DD + r) * DD;
            if (tid < a0) o[tid] = (tid == 0) ? c0v * d0 * dr : 0.0f;
            float4 z = make_float4(0.f, 0.f, 0.f, 0.f);
            for (int k = tid; k < nv; k += 256) {
                float4 w = z;
                if (a0 == 0 && k == 0) w.x = c0v * d0 * dr;
                *reinterpret_cast<float4*>(o + a0 + (k << 2)) = w;
            }
            for (int c = ct + tid; c < DD; c += 256) o[c] = 0.0f;
        }
        __syncthreads();
        // pass 2: scatter 152 nonzeros per row (train + diagonal block)
        for (int jj = 0; jj < 16; jj++) {
            int i = i_min + 4 * jj;
            int r = 1 + i * NN + n;
            float dr = dvh[r];
            float* o = out + (size_t)(h * DD + r) * DD;
            int Ssc = (60 - 4 * jj) * NN + sigma - 1;
            if (tid < 128) {
                int c = 25 * (tid + 1);            // cc%25==24 train
                o[c] = shp[Ssc + c] * dvh[c] * dr;
            } else if (tid < 152) {
                int m = tid - 128;                 // diagonal block, m=0..23
                int c = 1 + i * NN + m;
                o[c] = shp[Ssc + c] * dvh[c] * dr;
            }
        }
    }
}

extern "C" void kernel_launch(void* const* d_in, const int* in_sizes, int n_in,
                              void* d_out, int out_size) {
    const float* mat   = (const float*)d_in[0];  // (8,25,25)
    const float* te    = (const float*)d_in[1];  // (8,255)
    const float* W     = (const float*)d_in[2];  // (4,8)
    const float* bias  = (const float*)d_in[3];  // (4,)
    const float* minit = (const float*)d_in[4];  // (4,3201,3201)
    float* out = (float*)d_out;

    pm_k_main<<<104, 256>>>(mat, te, W, bias, minit);
    pm_k_out<<<804, 256>>>(minit, out);
}